// round 6
// baseline (speedup 1.0000x reference)
#include <cuda_runtime.h>
#include <cuda_bf16.h>
#include <math.h>

typedef unsigned long long ull;

// packed fp32x2 ops (Blackwell sm_10x; ptxas never emits FFMA2 on its own)
#define FFMA2(d, a, b) \
    asm("fma.rn.f32x2 %0, %1, %2, %0;" : "+l"(d) : "l"(a), "l"(b))
#define FADD2(d, a, b) \
    asm("add.rn.f32x2 %0, %1, %2;" : "=l"(d) : "l"(a), "l"(b))
#define PACK2(d, s) \
    asm("mov.b64 %0, {%1, %1};" : "=l"(d) : "f"(s))

// Problem constants
#define BB 64
#define SS 512
#define II 512
#define HH 512
#define LL 2
#define MROWS (BB * LL)          // 128 recurrence rows
#define MX (BB * SS)             // 32768 rows of xa GEMM

// ---------------- scratch (static device memory; no allocs allowed) ----------
__device__ float g_xa[(size_t)MX * HH];       // 64 MB: xa = x @ W_ih^T + b_ih
__device__ float g_h[2][MROWS * HH];          // double-buffered recurrent state

// per-row-group barrier state (16 groups of 8 CTAs), padded slots
#define RB_GROUPS 16
__device__ unsigned g_cnt[RB_GROUPS * 32];    // arrival counts (return to 0)
__device__ unsigned g_sense[RB_GROUPS * 32];  // 512 toggles -> back to 0

// =============================================================================
// Kernel A: xa[m][n] = sum_k x[m][k] * W_ih[n][k] + b_ih[n]
// 128x128 tile, BK=8, double buffered, 8x8 per thread via FFMA2, 256 threads.
// =============================================================================
__global__ void __launch_bounds__(256) gemm_xa_kernel(
    const float* __restrict__ A,      // [MX][II]
    const float* __restrict__ Bw,     // [HH][II]
    const float* __restrict__ bias)   // [HH]
{
    __shared__ float As[2][8][128];
    __shared__ float Bs[2][8][128];

    const int K = II;
    const int N = HH;
    const int m0 = blockIdx.y * 128;
    const int n0 = blockIdx.x * 128;
    const int tid = threadIdx.x;
    const int tx = tid & 15;
    const int ty = tid >> 4;
    const int lrow = tid >> 1;
    const int lkq  = (tid & 1) * 4;

    const float* Aptr = A + (size_t)(m0 + lrow) * K + lkq;
    const float* Bptr = Bw + (size_t)(n0 + lrow) * K + lkq;

    // acc2[i][p] packs columns (2p, 2p+1) of output col group tx*8
    ull acc2[8][4];
#pragma unroll
    for (int i = 0; i < 8; i++)
#pragma unroll
        for (int p = 0; p < 4; p++) acc2[i][p] = 0ull;

    {
        float4 av = *(const float4*)Aptr;
        float4 bv = *(const float4*)Bptr;
        As[0][lkq + 0][lrow] = av.x; As[0][lkq + 1][lrow] = av.y;
        As[0][lkq + 2][lrow] = av.z; As[0][lkq + 3][lrow] = av.w;
        Bs[0][lkq + 0][lrow] = bv.x; Bs[0][lkq + 1][lrow] = bv.y;
        Bs[0][lkq + 2][lrow] = bv.z; Bs[0][lkq + 3][lrow] = bv.w;
    }
    __syncthreads();

    for (int kb = 8; kb <= K; kb += 8) {
        const int buf = ((kb >> 3) & 1) ^ 1;
        float4 av2, bv2;
        const bool more = (kb < K);
        if (more) {
            av2 = *(const float4*)(Aptr + kb);
            bv2 = *(const float4*)(Bptr + kb);
        }
#pragma unroll
        for (int kk = 0; kk < 8; kk++) {
            float a[8];
            *(float4*)(a + 0) = *(const float4*)&As[buf][kk][ty * 8 + 0];
            *(float4*)(a + 4) = *(const float4*)&As[buf][kk][ty * 8 + 4];
            const ulonglong2 b01 = *(const ulonglong2*)&Bs[buf][kk][tx * 8 + 0];
            const ulonglong2 b23 = *(const ulonglong2*)&Bs[buf][kk][tx * 8 + 4];
#pragma unroll
            for (int i = 0; i < 8; i++) {
                ull aa; PACK2(aa, a[i]);
                FFMA2(acc2[i][0], aa, b01.x);
                FFMA2(acc2[i][1], aa, b01.y);
                FFMA2(acc2[i][2], aa, b23.x);
                FFMA2(acc2[i][3], aa, b23.y);
            }
        }
        if (more) {
            const int nb = buf ^ 1;
            As[nb][lkq + 0][lrow] = av2.x; As[nb][lkq + 1][lrow] = av2.y;
            As[nb][lkq + 2][lrow] = av2.z; As[nb][lkq + 3][lrow] = av2.w;
            Bs[nb][lkq + 0][lrow] = bv2.x; Bs[nb][lkq + 1][lrow] = bv2.y;
            Bs[nb][lkq + 2][lrow] = bv2.z; Bs[nb][lkq + 3][lrow] = bv2.w;
            __syncthreads();
        }
    }

    float4 bv0 = *(const float4*)&bias[n0 + tx * 8 + 0];
    float4 bv1 = *(const float4*)&bias[n0 + tx * 8 + 4];
#pragma unroll
    for (int i = 0; i < 8; i++) {
        float* Crow = g_xa + (size_t)(m0 + ty * 8 + i) * N + n0 + tx * 8;
        const float2 p0 = *(float2*)&acc2[i][0];
        const float2 p1 = *(float2*)&acc2[i][1];
        const float2 p2 = *(float2*)&acc2[i][2];
        const float2 p3 = *(float2*)&acc2[i][3];
        float4 c0, c1;
        c0.x = p0.x + bv0.x; c0.y = p0.y + bv0.y;
        c0.z = p1.x + bv0.z; c0.w = p1.y + bv0.w;
        c1.x = p2.x + bv1.x; c1.y = p2.y + bv1.y;
        c1.z = p3.x + bv1.z; c1.w = p3.y + bv1.w;
        *(float4*)(Crow + 0) = c0;
        *(float4*)(Crow + 4) = c1;
    }
}

// =============================================================================
// Kernel B: persistent recurrence, v4 (FFMA2).
// 128 CTAs = 16 row-groups (rb) x 8 col-blocks (gb).
// CTA: rows rb*8..+7, cols gb*64..+63, K=512.
// SMEM: Wt2 (k-pair interleaved, 128 KB, resident), hs[8][516], red[8][512].
// 256 threads: kq = tid>>5 (K-slice of 64 per warp),
//              rowg = (tid>>4)&1 (4 rows), colg = tid&15 (4 cols).
// Thread computes a 4x4 tile with even/odd-k packed f32x2 accumulators:
// both operands of each FFMA2 are contiguous 8B in smem -> zero pack instrs.
// Barrier is per-row-group (8 CTAs).
// =============================================================================
#define GB_CTAS 128
#define GRP 8                      // CTAs per barrier group

__global__ void __launch_bounds__(256, 1) rnn_persistent_kernel(
    const float* __restrict__ W_hh,   // [HH][HH]
    const float* __restrict__ b_hh,   // [HH]
    float* __restrict__ out)          // y then h_last
{
    extern __shared__ float sm[];
    // Wt2[(k>>1)*128 + c*2 + (k&1)] = W_hh[g0+c][k]   (128 KB)
    float* Wt2 = sm;
    float* hs  = sm + 512 * 64;        // [8][516] (padded)
    float* red = hs + 8 * 516;         // [8 kq][512 outputs]

    const int tid = threadIdx.x;
    const int gb  = blockIdx.x & 7;    // 8 col-blocks
    const int rb  = blockIdx.x >> 3;   // 16 row-groups
    const int g0  = gb * 64;
    const int row_base = rb * 8;

    // ---- one-time: load W slice into interleaved-pair layout ----
    {
        const int c  = tid & 63;
        const int k0 = tid >> 6;       // 0..3
        const float* wsrc = W_hh + (size_t)(g0 + c) * HH;
#pragma unroll 8
        for (int k = k0; k < 512; k += 4)
            Wt2[(k >> 1) * 128 + c * 2 + (k & 1)] = __ldg(wsrc + k);
    }

    // ---- compute-role indices ----
    const int kq    = tid >> 5;        // warp id = K-slice
    const int rowg  = (tid >> 4) & 1;
    const int colg  = tid & 15;
    const int kbase = kq * 64;
    const int r0    = rowg * 4;
    const int c0    = colg * 4;

    // ---- epilogue-role indices: outputs o = 2*tid, 2*tid+1 ----
    const int orow  = tid >> 5;        // local row 0..7 (one per warp)
    const int oc    = 2 * (tid & 31);  // local col pair
    const int grow  = row_base + orow; // global recurrence row
    const int b_idx = grow >> 1;       // batch
    const int l_idx = grow & 1;        // layer
    const int gcol  = g0 + oc;         // global column pair base

    const float2 bg  = *(const float2*)&b_hh[gcol];
    float2 xav = *(const float2*)&g_xa[((size_t)b_idx * SS + 0) * HH + gcol];

    unsigned* cnt = &g_cnt[rb * 32];
    unsigned* sns = &g_sense[rb * 32];
    unsigned  sense = 0;

    const size_t Y_ELEMS = (size_t)BB * SS * LL * HH;
    __syncthreads();

    for (int s = 0; s < SS; s++) {
        float v0, v1;
        if (s == 0) {
            v0 = tanhf(xav.x + bg.x);
            v1 = tanhf(xav.y + bg.y);
        } else {
            // wait for group (8 CTAs sharing rb) to finish step s-1
            if (tid == 0) {
                unsigned v;
                do {
                    asm volatile("ld.acquire.gpu.u32 %0, [%1];"
                                 : "=r"(v) : "l"(sns));
                } while (v != sense);
            }
            __syncthreads();

            // stage h rows (8 x 512 = 16 KB) from L2 into padded smem
            const float4* src =
                (const float4*)(&g_h[s & 1][(size_t)row_base * HH]);
#pragma unroll
            for (int j = 0; j < 4; j++) {
                const int idx = tid + j * 256;      // float4 index, 0..1023
                const int r   = idx >> 7;
                const int kk  = idx & 127;
                *(float4*)&hs[r * 516 + kk * 4] = __ldcg(src + idx);
            }
            __syncthreads();

            // 4x4 tile over K-slice [kbase, kbase+64); even/odd-k packed
            ull acc[4][4];
#pragma unroll
            for (int i = 0; i < 4; i++)
#pragma unroll
                for (int j = 0; j < 4; j++) acc[i][j] = 0ull;

            const float* hp = hs + r0 * 516 + kbase;
            const float* wp = Wt2 + kq * 4096 + colg * 8;
#pragma unroll 4
            for (int kk = 0; kk < 64; kk += 4) {
                // h pairs: .x = (h[kk],h[kk+1]), .y = (h[kk+2],h[kk+3])
                const ulonglong2 hA = *(const ulonglong2*)(hp + 0 * 516 + kk);
                const ulonglong2 hB = *(const ulonglong2*)(hp + 1 * 516 + kk);
                const ulonglong2 hC = *(const ulonglong2*)(hp + 2 * 516 + kk);
                const ulonglong2 hD = *(const ulonglong2*)(hp + 3 * 516 + kk);
                const float* wk = wp + (kk >> 1) * 128;
                const ulonglong2 wa = *(const ulonglong2*)(wk);        // cols c0,c0+1 @k2
                const ulonglong2 wb = *(const ulonglong2*)(wk + 4);    // cols c0+2,c0+3
                const ulonglong2 wc = *(const ulonglong2*)(wk + 128);  // k2+1
                const ulonglong2 wd = *(const ulonglong2*)(wk + 132);

                FFMA2(acc[0][0], hA.x, wa.x); FFMA2(acc[0][1], hA.x, wa.y);
                FFMA2(acc[0][2], hA.x, wb.x); FFMA2(acc[0][3], hA.x, wb.y);
                FFMA2(acc[1][0], hB.x, wa.x); FFMA2(acc[1][1], hB.x, wa.y);
                FFMA2(acc[1][2], hB.x, wb.x); FFMA2(acc[1][3], hB.x, wb.y);
                FFMA2(acc[2][0], hC.x, wa.x); FFMA2(acc[2][1], hC.x, wa.y);
                FFMA2(acc[2][2], hC.x, wb.x); FFMA2(acc[2][3], hC.x, wb.y);
                FFMA2(acc[3][0], hD.x, wa.x); FFMA2(acc[3][1], hD.x, wa.y);
                FFMA2(acc[3][2], hD.x, wb.x); FFMA2(acc[3][3], hD.x, wb.y);

                FFMA2(acc[0][0], hA.y, wc.x); FFMA2(acc[0][1], hA.y, wc.y);
                FFMA2(acc[0][2], hA.y, wd.x); FFMA2(acc[0][3], hA.y, wd.y);
                FFMA2(acc[1][0], hB.y, wc.x); FFMA2(acc[1][1], hB.y, wc.y);
                FFMA2(acc[1][2], hB.y, wd.x); FFMA2(acc[1][3], hB.y, wd.y);
                FFMA2(acc[2][0], hC.y, wc.x); FFMA2(acc[2][1], hC.y, wc.y);
                FFMA2(acc[2][2], hC.y, wd.x); FFMA2(acc[2][3], hC.y, wd.y);
                FFMA2(acc[3][0], hD.y, wc.x); FFMA2(acc[3][1], hD.y, wc.y);
                FFMA2(acc[3][2], hD.y, wd.x); FFMA2(acc[3][3], hD.y, wd.y);
            }

            // collapse even/odd halves, scatter partials (STS.128)
            float* rp = red + kq * 512 + r0 * 64 + c0;
#pragma unroll
            for (int i = 0; i < 4; i++) {
                const float2 q0 = *(float2*)&acc[i][0];
                const float2 q1 = *(float2*)&acc[i][1];
                const float2 q2 = *(float2*)&acc[i][2];
                const float2 q3 = *(float2*)&acc[i][3];
                float4 t;
                t.x = q0.x + q0.y; t.y = q1.x + q1.y;
                t.z = q2.x + q2.y; t.w = q3.x + q3.y;
                *(float4*)(rp + i * 64) = t;
            }
            __syncthreads();

            // reduce over 8 kq slices for outputs (orow, oc/oc+1) via ADD2
            const ull* q = (const ull*)(red + orow * 64 + oc);
            ull a2 = q[0];
#pragma unroll
            for (int z = 1; z < 8; z++) {
                FADD2(a2, a2, q[z * 256]);   // 256 ull = 512 floats
            }
            const float2 p = *(float2*)&a2;
            v0 = tanhf(p.x + xav.x + bg.x);
            v1 = tanhf(p.y + xav.y + bg.y);
        }

        // publish h for next step (straight to L2)
        {
            float2* hdst = (float2*)&g_h[(s + 1) & 1][(size_t)grow * HH + gcol];
            asm volatile("st.global.cg.v2.f32 [%0], {%1, %2};"
                         :: "l"(hdst), "f"(v0), "f"(v1));
        }
        __syncthreads();

        // group barrier arrival (release publishes this step's h writes)
        if (tid == 0) {
            unsigned old;
            asm volatile("atom.add.release.gpu.u32 %0, [%1], %2;"
                         : "=r"(old) : "l"(cnt), "r"(1u));
            if (old == GRP - 1u) {
                asm volatile("st.relaxed.gpu.u32 [%0], %1;"
                             :: "l"(cnt), "r"(0u));
                asm volatile("st.release.gpu.u32 [%0], %1;"
                             :: "l"(sns), "r"(sense ^ 1u));
            }
        }
        sense ^= 1u;

        // epilogue overlaps peers' spin: y writes + next xa prefetch
        {
            float2 yv; yv.x = v0; yv.y = v1;
            *(float2*)&out[(((size_t)b_idx * SS + s) * LL + l_idx) * HH + gcol] = yv;
            if (s == SS - 1) {
                *(float2*)&out[Y_ELEMS + (size_t)grow * HH + gcol] = yv;
            } else {
                xav = *(const float2*)&g_xa[((size_t)b_idx * SS + (s + 1)) * HH + gcol];
            }
        }
    }
}

// =============================================================================
// launch
// =============================================================================
extern "C" void kernel_launch(void* const* d_in, const int* in_sizes, int n_in,
                              void* d_out, int out_size)
{
    const float* x    = (const float*)d_in[0];
    const float* W_ih = (const float*)d_in[1];
    const float* b_ih = (const float*)d_in[2];
    const float* W_hh = (const float*)d_in[3];
    const float* b_hh = (const float*)d_in[4];
    float* out = (float*)d_out;

    // Kernel A: xa = x @ W_ih^T + b_ih
    dim3 gridA(HH / 128, MX / 128);
    gemm_xa_kernel<<<gridA, 256>>>(x, W_ih, b_ih);

    // Kernel B: persistent recurrence
    const int smemB = (512 * 64 + 8 * 516 + 8 * 512) * (int)sizeof(float);
    cudaFuncSetAttribute(rnn_persistent_kernel,
                         cudaFuncAttributeMaxDynamicSharedMemorySize, smemB);
    rnn_persistent_kernel<<<GB_CTAS, 256, smemB>>>(W_hh, b_hh, out);
}